// round 17
// baseline (speedup 1.0000x reference)
#include <cuda_runtime.h>
#include <cuda_fp16.h>
#include <cstdint>

#define HW    128
#define N_SP  16384
#define MP    4096
#define BATCH 4
#define L2E   1.4426950408889634f
#define NQ    (BATCH * N_SP)
#define NKT   32                 // key tiles of 128 per batch

#define PHI_TILE_B 4352          // 16 rows x 272B
#define G_TILE_B   10240         // 128 keys x 80B (40 f16: 32 g + pad; stride 80 = conflict-free)
#define NSUB       256           // subsample every 16th key (validated margin)

// ---------------- scratch ----------------
__device__ float         d_negK  [NQ];
__device__ float         d_phiSub[BATCH * NSUB * 8];
__device__ unsigned char d_thPk  [NQ * 32];
__device__ unsigned char d_phiPk [(size_t)BATCH * NKT * PHI_TILE_B];
__device__ unsigned char d_ghPk  [(size_t)BATCH * NKT * G_TILE_B];
__device__ float         d_part  [2 * 33 * NQ];   // [h][ch][gq], ch32 = l

#define PART(h,k) (d_part + ((size_t)((h)*33 + (k)) << 16))

// ---------------- helpers ----------------
typedef unsigned long long f2;
__device__ __forceinline__ f2 pack2(float a, float b) {
    f2 r; asm("mov.b64 %0,{%1,%2};" : "=l"(r) : "f"(a), "f"(b)); return r;
}
__device__ __forceinline__ void unpack2(f2 v, float& a, float& b) {
    asm("mov.b64 {%0,%1},%2;" : "=f"(a), "=f"(b) : "l"(v));
}
__device__ __forceinline__ f2 fma2(f2 a, f2 b, f2 c) {
    f2 d; asm("fma.rn.f32x2 %0,%1,%2,%3;" : "=l"(d) : "l"(a), "l"(b), "l"(c)); return d;
}
__device__ __forceinline__ f2 mul2(f2 a, f2 b) {
    f2 d; asm("mul.rn.f32x2 %0,%1,%2;" : "=l"(d) : "l"(a), "l"(b)); return d;
}
__device__ __forceinline__ unsigned h2u(float lo_v, float hi_v) {
    __half2 h = __floats2half2_rn(lo_v, hi_v);
    return *reinterpret_cast<unsigned*>(&h);
}
__device__ __forceinline__ float2 u2f2(unsigned u) {
    __half2 h = *reinterpret_cast<__half2*>(&u);
    return __half22float2(h);
}
__device__ __forceinline__ unsigned minh2(unsigned a, unsigned b) {
    unsigned r; asm("min.f16x2 %0,%1,%2;" : "=r"(r) : "r"(a), "r"(b)); return r;
}
__device__ __forceinline__ unsigned ex2h2(unsigned a) {
    unsigned r; asm("ex2.approx.f16x2 %0,%1;" : "=r"(r) : "r"(a)); return r;
}
__device__ __forceinline__ uint32_t smem_u32(const void* p) {
    uint32_t a;
    asm("{ .reg .u64 t; cvta.to.shared.u64 t, %1; cvt.u32.u64 %0, t; }" : "=r"(a) : "l"(p));
    return a;
}
__device__ __forceinline__ void cp16(uint32_t d, const void* s) {
    asm volatile("cp.async.cg.shared.global [%0],[%1],16;" :: "r"(d), "l"(s));
}
#define CP_COMMIT() asm volatile("cp.async.commit_group;" ::: "memory")
#define CP_WAIT0()  asm volatile("cp.async.wait_group 0;" ::: "memory")

__device__ __forceinline__ void mma16816(float d[4], const unsigned a[4], unsigned b0, unsigned b1) {
    asm volatile("mma.sync.aligned.m16n8k16.row.col.f32.f16.f16.f32 "
        "{%0,%1,%2,%3},{%4,%5,%6,%7},{%8,%9},{%0,%1,%2,%3};"
        : "+f"(d[0]), "+f"(d[1]), "+f"(d[2]), "+f"(d[3])
        : "r"(a[0]), "r"(a[1]), "r"(a[2]), "r"(a[3]), "r"(b0), "r"(b1));
}
__device__ __forceinline__ void ldm4t(unsigned r[4], uint32_t a) {
    asm volatile("ldmatrix.sync.aligned.m8n8.x4.trans.shared.b16 {%0,%1,%2,%3},[%4];"
        : "=r"(r[0]), "=r"(r[1]), "=r"(r[2]), "=r"(r[3]) : "r"(a));
}
__device__ __forceinline__ void ldm4(unsigned r[4], uint32_t a) {
    asm volatile("ldmatrix.sync.aligned.m8n8.x4.shared.b16 {%0,%1,%2,%3},[%4];"
        : "=r"(r[0]), "=r"(r[1]), "=r"(r[2]), "=r"(r[3]) : "r"(a));
}

// ================================================================================
// kconvpool: fused 1x1 convs + 2x2 maxpool + tile packing (validated R16).
// ================================================================================
#define CPAD 264
#define POOL_OFF 12288

__global__ void __launch_bounds__(256) kconvpool(
    const float* __restrict__ x, const float* __restrict__ wt,
    const float* __restrict__ wp, const float* __restrict__ wg)
{
    extern __shared__ float smf[];
    float* ws   = smf;
    float* pool = smf + POOL_OFF / 4;

    const int tid = threadIdx.x;
    for (int i = tid; i < 64 * 48; i += 256) {
        int c = i / 48, o = i % 48;
        float v = (o < 8)  ? wt[o * 64 + c]
                : (o < 16) ? wp[(o - 8) * 64 + c]
                           : wg[(o - 16) * 64 + c];
        ws[c * 48 + o] = v;
    }
    __syncthreads();

    const int blk = blockIdx.x;
    const int b   = blk >> 6;
    const int R   = blk & 63;
    const int t   = (b << 14) + R * 256 + tid;
    const int n   = R * 256 + tid;
    const float* xb = x + ((size_t)b * 64) * N_SP + n;

    f2 acc2[24];
    #pragma unroll
    for (int j = 0; j < 24; ++j) acc2[j] = 0ULL;
    #pragma unroll 4
    for (int c = 0; c < 64; ++c) {
        float xv = xb[(size_t)c * N_SP];
        f2 xv2 = pack2(xv, xv);
        const f2* w2 = reinterpret_cast<const f2*>(&ws[c * 48]);
        #pragma unroll
        for (int j = 0; j < 24; ++j)
            acc2[j] = fma2(xv2, w2[j], acc2[j]);
    }

    float tv[8];
    #pragma unroll
    for (int j = 0; j < 4; ++j) {
        float a, c2; unpack2(acc2[j], a, c2);
        tv[2*j] = a * L2E; tv[2*j+1] = c2 * L2E;
    }
    unsigned u[8];
    #pragma unroll
    for (int j = 0; j < 4; ++j) {
        unsigned h = h2u(tv[2*j], tv[2*j+1]);
        float2 back = u2f2(h);
        u[j]     = h;
        u[4 + j] = h2u(tv[2*j] - back.x, tv[2*j+1] - back.y);
    }
    uint4* dst = reinterpret_cast<uint4*>(d_thPk) + (size_t)t * 2;
    dst[0] = make_uint4(u[0], u[1], u[2], u[3]);
    dst[1] = make_uint4(u[4], u[5], u[6], u[7]);

    #pragma unroll
    for (int j = 0; j < 4; ++j) {
        float a, c2; unpack2(acc2[4 + j], a, c2);
        pool[(2*j)     * CPAD + tid] = a;
        pool[(2*j + 1) * CPAD + tid] = c2;
    }
    #pragma unroll
    for (int j = 0; j < 16; ++j) {
        float a, c2; unpack2(acc2[8 + j], a, c2);
        pool[(8 + 2*j)     * CPAD + tid] = a;
        pool[(8 + 2*j + 1) * CPAD + tid] = c2;
    }
    __syncthreads();

    if (tid < 64) {
        const int j   = tid;
        const int m   = R * 64 + j;
        const int kt  = m >> 7, row = m & 127;
        const int c0 = 2 * j, c2i = 128 + 2 * j;

        float pout[8];
        #pragma unroll
        for (int o = 0; o < 8; ++o) {
            const float* pr = pool + o * CPAD;
            pout[o] = fmaxf(fmaxf(pr[c0], pr[c0 + 1]), fmaxf(pr[c2i], pr[c2i + 1]));
        }
        if ((j & 15) == 0) {
            #pragma unroll
            for (int o = 0; o < 8; ++o)
                d_phiSub[(b * NSUB + (m >> 4)) * 8 + o] = pout[o];
        }
        {
            unsigned char* tb = d_phiPk + ((size_t)(b * NKT + kt)) * PHI_TILE_B;
            #pragma unroll
            for (int o = 0; o < 8; ++o) {
                __half h = __float2half_rn(pout[o]);
                __half l = __float2half_rn(pout[o] - __half2float(h));
                *reinterpret_cast<__half*>(tb + o * 272 + row * 2)       = h;
                *reinterpret_cast<__half*>(tb + (o + 8) * 272 + row * 2) = l;
            }
        }
        {
            unsigned hq[20];
            #pragma unroll
            for (int k = 0; k < 16; ++k) {
                const float* p0 = pool + (8 + 2*k) * CPAD;
                const float* p1 = pool + (9 + 2*k) * CPAD;
                float ge = fmaxf(fmaxf(p0[c0], p0[c0 + 1]), fmaxf(p0[c2i], p0[c2i + 1]));
                float go = fmaxf(fmaxf(p1[c0], p1[c0 + 1]), fmaxf(p1[c2i], p1[c2i + 1]));
                hq[k] = h2u(ge, go);
            }
            hq[16] = 0u;    // ones column no longer used (l computed in SIMT)
            hq[17] = hq[18] = hq[19] = 0u;
            uint4* gh = reinterpret_cast<uint4*>(d_ghPk + ((size_t)(b * NKT + kt)) * G_TILE_B + row * 80);
            #pragma unroll
            for (int k = 0; k < 5; ++k)
                gh[k] = make_uint4(hq[4*k], hq[4*k+1], hq[4*k+2], hq[4*k+3]);
        }
    }
}
#define CONVPOOL_SMEM (POOL_OFF + 40 * CPAD * 4)

// ================================================================================
// kqmax: per-query subsample max (every 16th key), f32x2 -> negK = 4 - mx
// ================================================================================
__global__ void __launch_bounds__(256) kqmax()
{
    __shared__ float phs[NSUB * 8];
    const int tid = threadIdx.x;
    const int gq = blockIdx.x * 256 + tid;
    const int b = gq >> 14;
    for (int k = tid; k < NSUB * 8; k += 256) phs[k] = d_phiSub[b * NSUB * 8 + k];
    __syncthreads();

    const uint4* u = reinterpret_cast<const uint4*>(d_thPk) + (size_t)gq * 2;
    uint4 uh = u[0], ul = u[1];
    f2 thp[4];
    {
        unsigned hs[4] = { uh.x, uh.y, uh.z, uh.w };
        unsigned ls[4] = { ul.x, ul.y, ul.z, ul.w };
        #pragma unroll
        for (int jj = 0; jj < 4; ++jj) {
            float2 fh = u2f2(hs[jj]);
            float2 fl = u2f2(ls[jj]);
            thp[jj] = pack2(fh.x + fl.x, fh.y + fl.y);
        }
    }
    float mx = -3.0e38f;
    #pragma unroll 4
    for (int m = 0; m < NSUB; ++m) {
        const f2* p = reinterpret_cast<const f2*>(&phs[m * 8]);
        f2 s2 = mul2(thp[0], p[0]);
        s2 = fma2(thp[1], p[1], s2);
        s2 = fma2(thp[2], p[2], s2);
        s2 = fma2(thp[3], p[3], s2);
        float sa, sb; unpack2(s2, sa, sb);
        mx = fmaxf(mx, sa + sb);
    }
    d_negK[gq] = 4.0f - mx;
}

// ================================================================================
// kattn: HMMA flash attention, split-K x2. l computed in SIMT f32 from beta
// fragments (ones-column MMA removed: 16 MMAs/chunk instead of 18).
// ================================================================================
#define OF_TH   0
#define OF_TILE 6144
#define TILEB   14592
#define OF_ATT  6144
#define SMEM_TOT 35328

__global__ void __launch_bounds__(128) kattn()
{
    extern __shared__ char smem_raw[];
    const uint32_t sb = smem_u32(smem_raw);

    const int tid  = threadIdx.x;
    const int lane = tid & 31;
    const int wid  = tid >> 5;
    const int qw   = wid * 32;
    const int blk  = blockIdx.x;
    const int h    = blk >> 9;
    const int qb   = blk & 511;
    const int b    = qb >> 7;
    const int gqb  = qb * 128;
    const int t0   = h * 16;

    {
        const uint4* src = reinterpret_cast<const uint4*>(d_thPk) + (size_t)(gqb + tid) * 2;
        uint4 a = src[0], c = src[1];
        *reinterpret_cast<uint4*>(smem_raw + OF_TH + tid * 48)      = a;
        *reinterpret_cast<uint4*>(smem_raw + OF_TH + tid * 48 + 16) = c;
    }
    const unsigned char* phiT = d_phiPk + (size_t)b * NKT * PHI_TILE_B;
    const unsigned char* ghT  = d_ghPk  + (size_t)b * NKT * G_TILE_B;
    {
        const unsigned char* ps = phiT + (size_t)t0 * PHI_TILE_B;
        const unsigned char* hs = ghT + (size_t)t0 * G_TILE_B;
        for (int k = tid; k < 272; k += 128) cp16(sb + OF_TILE + k * 16, ps + k * 16);
        #pragma unroll
        for (int k = 0; k < 5; ++k)
            cp16(sb + OF_TILE + 4352 + (tid + 128 * k) * 16, hs + (size_t)(tid + 128 * k) * 16);
        CP_COMMIT();
    }
    __syncthreads();

    unsigned thA[2][4];
    #pragma unroll
    for (int bk = 0; bk < 2; ++bk)
        ldm4(thA[bk], sb + OF_TH + (uint32_t)(qw + bk * 16 + (lane & 15)) * 48 + ((lane >> 4) << 4));

    float nk[4];
    #pragma unroll
    for (int r = 0; r < 4; ++r) nk[r] = d_negK[gqb + qw + r * 8 + (lane >> 2)];

    float acc[2][4][4];
    #pragma unroll
    for (int bk = 0; bk < 2; ++bk)
        #pragma unroll
        for (int jt = 0; jt < 4; ++jt)
            #pragma unroll
            for (int r = 0; r < 4; ++r) acc[bk][jt][r] = 0.0f;
    float lf[2][2] = {{0.0f, 0.0f}, {0.0f, 0.0f}};   // [bk][row-half] partial l

    const uint32_t lphi = (uint32_t)(lane & 15) * 272 + (uint32_t)((lane >> 4) << 3) * 2;
    const uint32_t lg4  = (uint32_t)(lane & 15) * 80 + (uint32_t)((lane >> 4) << 3) * 2;
    const unsigned CL15 = h2u(15.0f, 15.0f);

    for (int t = t0; t < t0 + 16; ++t) {
        const uint32_t CUR = sb + OF_TILE + (uint32_t)(t & 1) * TILEB;
        CP_WAIT0();
        __syncthreads();
        if (t + 1 < t0 + 16) {
            const uint32_t NXT = sb + OF_TILE + (uint32_t)((t + 1) & 1) * TILEB;
            const unsigned char* ps = phiT + (size_t)(t + 1) * PHI_TILE_B;
            const unsigned char* hs = ghT + (size_t)(t + 1) * G_TILE_B;
            for (int k = tid; k < 272; k += 128) cp16(NXT + k * 16, ps + k * 16);
            #pragma unroll
            for (int k = 0; k < 5; ++k)
                cp16(NXT + 4352 + (tid + 128 * k) * 16, hs + (size_t)(tid + 128 * k) * 16);
            CP_COMMIT();
        }

        #pragma unroll 2
        for (int c = 0; c < 8; ++c) {
            unsigned pb[4], gh01[4], gh23[4];
            ldm4t(pb, CUR + lphi + (uint32_t)c * 32);
            const uint32_t grow = CUR + 4352 + (uint32_t)c * 16 * 80;
            ldm4t(gh01, grow + lg4);
            ldm4t(gh23, grow + lg4 + 32);

            float s0[2][4], s1[2][4];
            #pragma unroll
            for (int bk = 0; bk < 2; ++bk) {
                const float nkA = nk[2 * bk], nkB = nk[2 * bk + 1];
                s0[bk][0] = nkA; s0[bk][1] = nkA; s0[bk][2] = nkB; s0[bk][3] = nkB;
                s1[bk][0] = nkA; s1[bk][1] = nkA; s1[bk][2] = nkB; s1[bk][3] = nkB;
                mma16816(s0[bk], thA[bk], pb[0], pb[1]);
                mma16816(s0[bk], thA[bk], pb[1], pb[0]);
                mma16816(s1[bk], thA[bk], pb[2], pb[3]);
                mma16816(s1[bk], thA[bk], pb[3], pb[2]);
            }
            #pragma unroll
            for (int bk = 0; bk < 2; ++bk) {
                unsigned bf[4];
                bf[0] = ex2h2(minh2(h2u(s0[bk][0], s0[bk][1]), CL15));   // row r
                bf[1] = ex2h2(minh2(h2u(s0[bk][2], s0[bk][3]), CL15));   // row r+8
                bf[2] = ex2h2(minh2(h2u(s1[bk][0], s1[bk][1]), CL15));   // row r
                bf[3] = ex2h2(minh2(h2u(s1[bk][2], s1[bk][3]), CL15));   // row r+8
                // l partials in f32 (exact cvt from the same f16 betas)
                float2 q0 = u2f2(bf[0]), q1 = u2f2(bf[1]),
                       q2 = u2f2(bf[2]), q3 = u2f2(bf[3]);
                lf[bk][0] += (q0.x + q0.y) + (q2.x + q2.y);
                lf[bk][1] += (q1.x + q1.y) + (q3.x + q3.y);
                mma16816(acc[bk][0], bf, gh01[0], gh01[1]);
                mma16816(acc[bk][1], bf, gh01[2], gh01[3]);
                mma16816(acc[bk][2], bf, gh23[0], gh23[1]);
                mma16816(acc[bk][3], bf, gh23[2], gh23[3]);
            }
        }
    }

    // reduce l across the 4 lanes of each row-quad
    #pragma unroll
    for (int bk = 0; bk < 2; ++bk)
        #pragma unroll
        for (int j = 0; j < 2; ++j) {
            lf[bk][j] += __shfl_xor_sync(0xffffffffu, lf[bk][j], 1);
            lf[bk][j] += __shfl_xor_sync(0xffffffffu, lf[bk][j], 2);
        }

    __syncthreads();
    float* ATT = reinterpret_cast<float*>(smem_raw + OF_ATT);
    #pragma unroll
    for (int bk = 0; bk < 2; ++bk) {
        const int r0 = qw + bk * 16 + (lane >> 2);
        const int col = (lane & 3) * 2;
        #pragma unroll
        for (int jt = 0; jt < 4; ++jt) {
            *reinterpret_cast<float2*>(ATT + r0 * 34 + jt * 8 + col) =
                make_float2(acc[bk][jt][0], acc[bk][jt][1]);
            *reinterpret_cast<float2*>(ATT + (r0 + 8) * 34 + jt * 8 + col) =
                make_float2(acc[bk][jt][2], acc[bk][jt][3]);
        }
        if ((lane & 3) == 0) {
            ATT[r0 * 34 + 32]       = lf[bk][0];
            ATT[(r0 + 8) * 34 + 32] = lf[bk][1];
        }
    }
    __syncthreads();

    const int gq = gqb + tid;
    const float* row = ATT + tid * 34;
    #pragma unroll
    for (int k = 0; k < 33; ++k)
        PART(h, k)[gq] = row[k];
}

// ================================================================================
// kcomb: merge halves + w_o + residual. 512 thr/CTA: 2 threads per query,
// each handling 32 of 64 output channels (2x latency hiding).
// ================================================================================
__global__ void __launch_bounds__(512) kcomb(
    const float* __restrict__ x, const float* __restrict__ wo,
    const float* __restrict__ gamma, float* __restrict__ out)
{
    __shared__ float ws[64 * 32];
    const int tid = threadIdx.x;
    reinterpret_cast<float4*>(ws)[tid] = reinterpret_cast<const float4*>(wo)[tid];
    __syncthreads();

    const int qi   = tid & 255;
    const int half = tid >> 8;
    const int gq = blockIdx.x * 256 + qi;
    const int b  = gq >> 14;
    const int n  = gq & (N_SP - 1);

    f2 acc[16];
    #pragma unroll
    for (int k = 0; k < 16; ++k) {
        float a = PART(0, 2 * k + 0)[gq] + PART(1, 2 * k + 0)[gq];
        float c = PART(0, 2 * k + 1)[gq] + PART(1, 2 * k + 1)[gq];
        acc[k] = pack2(a, c);
    }
    const float l   = fmaxf(PART(0, 32)[gq] + PART(1, 32)[gq], 1e-20f);
    const float inv = 1.0f / l;
    const float gam = gamma[0];

    const float* xq = x   + ((size_t)b * 64 + half * 32) * N_SP + n;
    float*       oq = out + ((size_t)b * 64 + half * 32) * N_SP + n;

    #pragma unroll 4
    for (int k = 0; k < 32; ++k) {
        const ulonglong2* w2 = reinterpret_cast<const ulonglong2*>(ws + (half * 32 + k) * 32);
        f2 o2 = 0ULL;
        #pragma unroll
        for (int j = 0; j < 8; ++j) {
            ulonglong2 wv = w2[j];
            o2 = fma2(acc[2 * j + 0], wv.x, o2);
            o2 = fma2(acc[2 * j + 1], wv.y, o2);
        }
        float oa, ob; unpack2(o2, oa, ob);
        oq[(size_t)k * N_SP] = fmaf(gam, (oa + ob) * inv, xq[(size_t)k * N_SP]);
    }
}

// ================================================================================
extern "C" void kernel_launch(void* const* d_in, const int* in_sizes, int n_in,
                              void* d_out, int out_size)
{
    const float* x     = (const float*)d_in[0];
    const float* wt    = (const float*)d_in[1];
    const float* wp    = (const float*)d_in[2];
    const float* wg    = (const float*)d_in[3];
    const float* wo    = (const float*)d_in[4];
    const float* gamma = (const float*)d_in[5];
    float* out = (float*)d_out;

    static int cfg = 0;
    if (!cfg) {
        cudaFuncSetAttribute(kattn, cudaFuncAttributeMaxDynamicSharedMemorySize, SMEM_TOT);
        cudaFuncSetAttribute(kconvpool, cudaFuncAttributeMaxDynamicSharedMemorySize, CONVPOOL_SMEM);
        cfg = 1;
    }
    kconvpool<<<256, 256, CONVPOOL_SMEM>>>(x, wt, wp, wg);
    kqmax<<<256, 256>>>();
    kattn<<<1024, 128, SMEM_TOT>>>();
    kcomb<<<256, 512>>>(x, wo, gamma, out);
}